// round 1
// baseline (speedup 1.0000x reference)
#include <cuda_runtime.h>
#include <cuda_bf16.h>

// Conv3x3 (stride1, pad1, no bias) + fused PixelUnshuffle(2)
// x: (8, 96, 256, 256) f32, W: (48, 96, 3, 3) f32
// out: (8, 192, 128, 128) f32 where
//   out[b, oc*4 + (h&1)*2 + (w&1), h>>1, w>>1] = conv(x,W)[b, oc, h, w]
//
// Block: 16x32 output tile, all 48 oc.
// Threads: 256 = 2 oc-groups (24 oc each) x 128 pixel slots (16 rows x 8 slot-cols),
//          each thread computes 4 consecutive-in-w pixels for its 24 oc.
// Smem: input chunk [8 ic][18 rows][36 cols(pad)] + weight chunk [48 oc][8 ic][12(pad)]

#define BATCH 8
#define IC    96
#define HH    256
#define WW    256
#define OC    48
#define TH    16
#define TW    32
#define ICC   8          // ic chunk
#define NCHUNK (IC / ICC)

__global__ void __launch_bounds__(256, 1)
conv3x3_unshuffle_kernel(const float* __restrict__ x,
                         const float* __restrict__ Wg,
                         float* __restrict__ out)
{
    __shared__ float xs[ICC][TH + 2][TW + 4];   // 8*18*36 floats = 20736 B (cols 34,35 pad)
    __shared__ float ws[OC][ICC][12];           // 48*8*12 floats = 18432 B (9 used, pad to 12)

    const int tid = threadIdx.x;
    const int ocg = tid >> 7;          // 0 or 1 (uniform per warp)
    const int slot = tid & 127;        // 0..127
    const int pr = slot >> 3;          // pixel row in tile 0..15
    const int sc = slot & 7;           // slot col 0..7 -> pixels cols sc*4 .. sc*4+3

    const int w0 = blockIdx.x * TW;
    const int h0 = blockIdx.y * TH;
    const int b  = blockIdx.z;

    float acc[24][4];
#pragma unroll
    for (int oc = 0; oc < 24; ++oc)
#pragma unroll
        for (int p = 0; p < 4; ++p)
            acc[oc][p] = 0.0f;

    const long long x_b = (long long)b * IC * HH * WW;

    for (int chunk = 0; chunk < NCHUNK; ++chunk) {
        const int ic0 = chunk * ICC;
        __syncthreads();

        // ---- stage input tile (18 x 34 per ic, zero-padded at borders) ----
        {
            const int total = ICC * (TH + 2) * (TW + 2);   // 8*18*34 = 4896
            for (int i = tid; i < total; i += 256) {
                const int ic  = i / ((TH + 2) * (TW + 2));
                const int rem = i % ((TH + 2) * (TW + 2));
                const int row = rem / (TW + 2);
                const int col = rem % (TW + 2);
                const int h = h0 - 1 + row;
                const int w = w0 - 1 + col;
                float v = 0.0f;
                if ((unsigned)h < HH && (unsigned)w < WW) {
                    v = x[x_b + ((long long)(ic0 + ic) * HH + h) * WW + w];
                }
                xs[ic][row][col] = v;
            }
        }
        // ---- stage weight chunk ----
        {
            const int total = OC * ICC * 9;                 // 3456
            for (int i = tid; i < total; i += 256) {
                const int oc  = i / (ICC * 9);
                const int rem = i % (ICC * 9);
                const int ic  = rem / 9;
                const int k   = rem % 9;
                ws[oc][ic][k] = Wg[oc * (IC * 9) + (ic0 + ic) * 9 + k];
            }
        }
        __syncthreads();

        // ---- compute: 8 ics, 24 oc, 4 px, 9 taps ----
#pragma unroll 1
        for (int ic = 0; ic < ICC; ++ic) {
            float xr0[8], xr1[8], xr2[8];
            {
                const float4* r0 = (const float4*)&xs[ic][pr + 0][sc * 4];
                const float4* r1 = (const float4*)&xs[ic][pr + 1][sc * 4];
                const float4* r2 = (const float4*)&xs[ic][pr + 2][sc * 4];
                float4 a, c;
                a = r0[0]; c = r0[1];
                xr0[0]=a.x; xr0[1]=a.y; xr0[2]=a.z; xr0[3]=a.w; xr0[4]=c.x; xr0[5]=c.y; xr0[6]=c.z; xr0[7]=c.w;
                a = r1[0]; c = r1[1];
                xr1[0]=a.x; xr1[1]=a.y; xr1[2]=a.z; xr1[3]=a.w; xr1[4]=c.x; xr1[5]=c.y; xr1[6]=c.z; xr1[7]=c.w;
                a = r2[0]; c = r2[1];
                xr2[0]=a.x; xr2[1]=a.y; xr2[2]=a.z; xr2[3]=a.w; xr2[4]=c.x; xr2[5]=c.y; xr2[6]=c.z; xr2[7]=c.w;
            }
#pragma unroll
            for (int oc = 0; oc < 24; ++oc) {
                const float* wp = &ws[ocg * 24 + oc][ic][0];
                const float4 wa = *(const float4*)(wp);      // taps 0..3
                const float4 wb = *(const float4*)(wp + 4);  // taps 4..7
                const float  w8 = wp[8];                     // tap 8
#pragma unroll
                for (int p = 0; p < 4; ++p) {
                    float s = acc[oc][p];
                    s = fmaf(wa.x, xr0[p    ], s);
                    s = fmaf(wa.y, xr0[p + 1], s);
                    s = fmaf(wa.z, xr0[p + 2], s);
                    s = fmaf(wa.w, xr1[p    ], s);
                    s = fmaf(wb.x, xr1[p + 1], s);
                    s = fmaf(wb.y, xr1[p + 2], s);
                    s = fmaf(wb.z, xr2[p    ], s);
                    s = fmaf(wb.w, xr2[p + 1], s);
                    s = fmaf(w8,   xr2[p + 2], s);
                    acc[oc][p] = s;
                }
            }
        }
    }

    // ---- epilogue: fused PixelUnshuffle(2) store ----
    // out[b, oc*4 + (h&1)*2 + (w&1), h>>1, w>>1]
    const int h  = h0 + pr;
    const int i2 = (h & 1) * 2;
    const int h2 = h >> 1;
    const int wbase = w0 + sc * 4;          // even
    const int w2base = wbase >> 1;
#pragma unroll
    for (int oc = 0; oc < 24; ++oc) {
        const int oc_g = ocg * 24 + oc;
#pragma unroll
        for (int p = 0; p < 4; ++p) {
            const int ch = oc_g * 4 + i2 + (p & 1);
            const int w2 = w2base + (p >> 1);
            out[(((long long)b * 192 + ch) * 128 + h2) * 128 + w2] = acc[oc][p];
        }
    }
}

extern "C" void kernel_launch(void* const* d_in, const int* in_sizes, int n_in,
                              void* d_out, int out_size)
{
    const float* x  = (const float*)d_in[0];
    const float* Wg = (const float*)d_in[1];
    float* out = (float*)d_out;

    dim3 grid(WW / TW, HH / TH, BATCH);   // (8, 16, 8)
    conv3x3_unshuffle_kernel<<<grid, 256>>>(x, Wg, out);
}